// round 3
// baseline (speedup 1.0000x reference)
#include <cuda_runtime.h>
#include <cuda_bf16.h>

#define N_RELS 64
#define REL_STRIDE4 3   // 3 float4 per relation = 48B (M row + beta packed in .w)

// Branchless sparsemax for d=3, reduced-op form.
// Faithful to: ksup = sum_k [1 + k*zs_k > cs_k], tau = (cs[ksup-1]-1)/ksup
// using cs2 = sum (sort-invariant), z0 = max, z2 = min, z1 = sum-max-min,
// s2: 1+2z1 > z0+z1  <=>  1+z1 > z0 ;  s3: 1+3z2 > sum.  (s3 => s2)
static __device__ __forceinline__ void sparsemax3(float x0, float x1, float x2,
                                                  float &o0, float &o1, float &o2) {
    float mx  = fmaxf(fmaxf(x0, x1), x2);
    float mn  = fminf(fminf(x0, x1), x2);
    float sum = x0 + x1 + x2;
    float z1  = sum - mx - mn;
    bool s2 = (1.0f + z1) > mx;
    bool s3 = (1.0f + 3.0f * mn) > sum;
    float csk = mx + (s2 ? z1 : 0.0f) + (s3 ? mn : 0.0f);  // cs[k-1]
    float rk  = s3 ? (1.0f / 3.0f) : (s2 ? 0.5f : 1.0f);   // 1/k
    float tau = (csk - 1.0f) * rk;
    o0 = fmaxf(x0 - tau, 0.0f);
    o1 = fmaxf(x1 - tau, 0.0f);
    o2 = fmaxf(x2 - tau, 0.0f);
}

static __device__ __forceinline__ void row_compute(
    float p0, float p1, float p2,
    float h0, float h1, float h2,
    const float4 *__restrict__ relp,
    float zeps, float sf,
    float &a0, float &a1, float &a2)
{
    float4 m0 = relp[0];   // {M00,M01,M02, beta0}
    float4 m1 = relp[1];   // {M10,M11,M12, beta1}
    float4 m2 = relp[2];   // {M20,M21,M22, beta2}

    // c = M[rel] @ child
    float c0 = m0.x * h0 + m0.y * h1 + m0.z * h2;
    float c1 = m1.x * h0 + m1.y * h1 + m1.z * h2;
    float c2 = m2.x * h0 + m2.y * h1 + m2.z * h2;
    sparsemax3(c0, c1, c2, c0, c1, c2);
    // (second sparsemax is an exact identity on a simplex point — dropped)
    sparsemax3(p0, p1, p2, p0, p1, p2);

    // alpha = (1-b)*p + b*c == p + b*(c-p)
    a0 = p0 + m0.w * (c0 - p0);
    a1 = p1 + m1.w * (c1 - p1);
    a2 = p2 + m2.w * (c2 - p2);

    // entropy of clamped normalized mixture (base-2, fold ln2 into the divide)
    float w0 = fmaxf(p0 + c0, zeps);
    float w1 = fmaxf(p1 + c1, zeps);
    float w2 = fmaxf(p2 + c2, zeps);
    float inv = __fdividef(1.0f, w0 + w1 + w2);
    w0 *= inv; w1 *= inv; w2 *= inv;
    float t2 = w0 * __log2f(w0) + w1 * __log2f(w1) + w2 * __log2f(w2); // negative

    float dot = p0 * c0 + p1 * c1 + p2 * c2;
    float pp  = p0 * p0 + p1 * p1 + p2 * p2;
    float cc  = c0 * c0 + c1 * c1 + c2 * c2;
    float nrm = fmaxf(__fsqrt_rn(pp) * __fsqrt_rn(cc), 1e-10f);
    // scale = sf * (0.1 + dot/nrm) / ent  ==  sf*(0.1*nrm + dot) / (nrm * -ln2 * t2)
    float num = sf * (0.1f * nrm + dot);
    float den = nrm * (-0.69314718056f) * t2;
    float scale = __fdividef(num, den);

    a0 = fmaxf(a0 * scale, 0.001f);
    a1 = fmaxf(a1 * scale, 0.001f);
    a2 = fmaxf(a2 * scale, 0.001f);
}

__global__ void __launch_bounds__(256, 6)
alpha_kernel(const float *__restrict__ prnt,
             const float *__restrict__ child,
             const float *__restrict__ Mg,
             const float *__restrict__ betag,
             const float *__restrict__ zeps_p,
             const float *__restrict__ sf_p,
             const int *__restrict__ rels,
             float *__restrict__ out,
             int n, int nquads)
{
    // Per-rel record: 3 float4 = {M_row_i, beta_i}. 48B stride -> starting
    // 16B chunk = rel*3 mod 8, cycles all 8 bank groups.
    __shared__ float4 sRel[N_RELS * REL_STRIDE4];
    {
        float *sF = reinterpret_cast<float *>(sRel);
        for (int i = threadIdx.x; i < N_RELS * 12; i += blockDim.x) {
            int r = i / 12, j = i % 12;
            int row = j >> 2, c = j & 3;
            sF[r * 12 + j] = (c < 3) ? Mg[r * 9 + row * 3 + c]
                                     : betag[r * 3 + row];
        }
    }
    __syncthreads();

    const float zeps = __ldg(zeps_p);
    const float sf   = __ldg(sf_p);

    int q = blockIdx.x * blockDim.x + threadIdx.x;

    if (q < nquads) {
        const float4 *p4 = reinterpret_cast<const float4 *>(prnt)  + (size_t)q * 3;
        const float4 *c4 = reinterpret_cast<const float4 *>(child) + (size_t)q * 3;
        float4 pA = p4[0], pB = p4[1], pC = p4[2];
        float4 cA = c4[0], cB = c4[1], cC = c4[2];
        int4 r4 = reinterpret_cast<const int4 *>(rels)[q];

        float pv[12] = {pA.x, pA.y, pA.z, pA.w, pB.x, pB.y, pB.z, pB.w,
                        pC.x, pC.y, pC.z, pC.w};
        float cv[12] = {cA.x, cA.y, cA.z, cA.w, cB.x, cB.y, cB.z, cB.w,
                        cC.x, cC.y, cC.z, cC.w};
        int rr[4] = {r4.x, r4.y, r4.z, r4.w};
        float ov[12];

#pragma unroll
        for (int i = 0; i < 4; i++) {
            row_compute(pv[3 * i], pv[3 * i + 1], pv[3 * i + 2],
                        cv[3 * i], cv[3 * i + 1], cv[3 * i + 2],
                        &sRel[rr[i] * REL_STRIDE4], zeps, sf,
                        ov[3 * i], ov[3 * i + 1], ov[3 * i + 2]);
        }

        float4 *o4 = reinterpret_cast<float4 *>(out) + (size_t)q * 3;
        o4[0] = make_float4(ov[0], ov[1], ov[2],  ov[3]);
        o4[1] = make_float4(ov[4], ov[5], ov[6],  ov[7]);
        o4[2] = make_float4(ov[8], ov[9], ov[10], ov[11]);
    }

    // scalar tail (n % 4 rows) — empty for N = 8,000,000 but kept general
    int rem = n - nquads * 4;
    if (q < rem) {
        int i = nquads * 4 + q;
        float a0, a1, a2;
        row_compute(prnt[3 * i], prnt[3 * i + 1], prnt[3 * i + 2],
                    child[3 * i], child[3 * i + 1], child[3 * i + 2],
                    &sRel[rels[i] * REL_STRIDE4], zeps, sf, a0, a1, a2);
        out[3 * i] = a0; out[3 * i + 1] = a1; out[3 * i + 2] = a2;
    }
}

extern "C" void kernel_launch(void* const* d_in, const int* in_sizes, int n_in,
                              void* d_out, int out_size) {
    // metadata order: prnt_probs, child_probs, M, beta, z_epsilon, scale_factor, rels, var_sfx
    const float *prnt  = (const float *)d_in[0];
    const float *child = (const float *)d_in[1];
    const float *Mg    = (const float *)d_in[2];
    const float *betag = (const float *)d_in[3];
    const float *zeps  = (const float *)d_in[4];
    const float *sf    = (const float *)d_in[5];
    const int   *rels  = (const int *)d_in[6];
    float *out = (float *)d_out;

    int n = in_sizes[6];
    int nquads = n / 4;
    int work = nquads > 0 ? nquads : 1;
    int threads = 256;
    int blocks = (work + threads - 1) / threads;

    alpha_kernel<<<blocks, threads>>>(prnt, child, Mg, betag, zeps, sf, rels,
                                      out, n, nquads);
}

// round 4
// speedup vs baseline: 1.1241x; 1.1241x over previous
#include <cuda_runtime.h>
#include <cuda_bf16.h>

#define N_RELS 64
#define REL_STRIDE4 3   // 3 float4 per relation = 48B (M row + beta packed in .w)

// Sparsemax for d=3 via closed-form threshold:
//   tau = max_k (cs_k - 1)/k   (equals reference's (cs[ksup-1]-1)/ksup, since
//   support at k+1  <=>  (cs_{k+1}-1)/(k+1) > (cs_k-1)/k, and support is
//   prefix-closed -> the running max stops exactly at k = ksup).
// cs1 = mx, cs2 = sum - mn, cs3 = sum. No predicates, no selects.
static __device__ __forceinline__ void sparsemax3(float x0, float x1, float x2,
                                                  float &o0, float &o1, float &o2) {
    float mx  = fmaxf(fmaxf(x0, x1), x2);
    float mn  = fminf(fminf(x0, x1), x2);
    float sum = x0 + x1 + x2;
    float t1 = mx - 1.0f;
    float t2 = (sum - mn - 1.0f) * 0.5f;
    float t3 = (sum - 1.0f) * (1.0f / 3.0f);
    float tau = fmaxf(t1, fmaxf(t2, t3));
    o0 = fmaxf(x0 - tau, 0.0f);
    o1 = fmaxf(x1 - tau, 0.0f);
    o2 = fmaxf(x2 - tau, 0.0f);
}

static __device__ __forceinline__ void row_compute(
    float p0, float p1, float p2,
    float h0, float h1, float h2,
    const float4 *__restrict__ relp,
    float zeps, float sf,
    float &a0, float &a1, float &a2)
{
    float4 m0 = relp[0];   // {M00,M01,M02, beta0}
    float4 m1 = relp[1];   // {M10,M11,M12, beta1}
    float4 m2 = relp[2];   // {M20,M21,M22, beta2}

    // c = M[rel] @ child
    float c0 = m0.x * h0 + m0.y * h1 + m0.z * h2;
    float c1 = m1.x * h0 + m1.y * h1 + m1.z * h2;
    float c2 = m2.x * h0 + m2.y * h1 + m2.z * h2;
    sparsemax3(c0, c1, c2, c0, c1, c2);
    // (second sparsemax is an exact identity on a simplex point — dropped)
    sparsemax3(p0, p1, p2, p0, p1, p2);

    // alpha = (1-b)*p + b*c == p + b*(c-p)
    a0 = p0 + m0.w * (c0 - p0);
    a1 = p1 + m1.w * (c1 - p1);
    a2 = p2 + m2.w * (c2 - p2);

    // entropy of clamped normalized mixture (base-2; ln2 folded into divide)
    float w0 = fmaxf(p0 + c0, zeps);
    float w1 = fmaxf(p1 + c1, zeps);
    float w2 = fmaxf(p2 + c2, zeps);
    float inv = __fdividef(1.0f, w0 + w1 + w2);
    w0 *= inv; w1 *= inv; w2 *= inv;
    float t2 = w0 * __log2f(w0) + w1 * __log2f(w1) + w2 * __log2f(w2); // < 0

    // cosine: sparsemax outputs sum to 1 => max comp >= 1/3 => pp*cc >= 1/81,
    // so the reference's max(nrm, 1e-10) guard is provably inactive.
    float dot = p0 * c0 + p1 * c1 + p2 * c2;
    float pp  = p0 * p0 + p1 * p1 + p2 * p2;
    float cc  = c0 * c0 + c1 * c1 + c2 * c2;
    float rq  = rsqrtf(pp * cc);
    float cosv = 0.1f + dot * rq;
    // scale = sf * cosv / (-ln2 * t2)
    float scale = __fdividef(sf * cosv, -0.69314718056f * t2);

    a0 = fmaxf(a0 * scale, 0.001f);
    a1 = fmaxf(a1 * scale, 0.001f);
    a2 = fmaxf(a2 * scale, 0.001f);
}

__global__ void __launch_bounds__(256, 6)
alpha_kernel(const float *__restrict__ prnt,
             const float *__restrict__ child,
             const float *__restrict__ Mg,
             const float *__restrict__ betag,
             const float *__restrict__ zeps_p,
             const float *__restrict__ sf_p,
             const int *__restrict__ rels,
             float *__restrict__ out,
             int n, int nquads)
{
    // Per-rel record: 3 float4 = {M_row_i, beta_i}. 48B stride -> starting
    // 16B chunk = rel*3 mod 8, cycles all 8 bank groups.
    __shared__ float4 sRel[N_RELS * REL_STRIDE4];
    {
        float *sF = reinterpret_cast<float *>(sRel);
        for (int i = threadIdx.x; i < N_RELS * 12; i += blockDim.x) {
            int r = i / 12, j = i % 12;
            int row = j >> 2, c = j & 3;
            sF[r * 12 + j] = (c < 3) ? Mg[r * 9 + row * 3 + c]
                                     : betag[r * 3 + row];
        }
    }
    __syncthreads();

    const float zeps = __ldg(zeps_p);
    const float sf   = __ldg(sf_p);

    int q = blockIdx.x * blockDim.x + threadIdx.x;

    if (q < nquads) {
        const float4 *p4 = reinterpret_cast<const float4 *>(prnt)  + (size_t)q * 3;
        const float4 *c4 = reinterpret_cast<const float4 *>(child) + (size_t)q * 3;
        // read-once stream: evict-first
        float4 pA = __ldcs(p4 + 0), pB = __ldcs(p4 + 1), pC = __ldcs(p4 + 2);
        float4 cA = __ldcs(c4 + 0), cB = __ldcs(c4 + 1), cC = __ldcs(c4 + 2);
        int4 r4 = __ldcs(reinterpret_cast<const int4 *>(rels) + q);

        float pv[12] = {pA.x, pA.y, pA.z, pA.w, pB.x, pB.y, pB.z, pB.w,
                        pC.x, pC.y, pC.z, pC.w};
        float cv[12] = {cA.x, cA.y, cA.z, cA.w, cB.x, cB.y, cB.z, cB.w,
                        cC.x, cC.y, cC.z, cC.w};
        int rr[4] = {r4.x, r4.y, r4.z, r4.w};
        float ov[12];

#pragma unroll
        for (int i = 0; i < 4; i++) {
            row_compute(pv[3 * i], pv[3 * i + 1], pv[3 * i + 2],
                        cv[3 * i], cv[3 * i + 1], cv[3 * i + 2],
                        &sRel[rr[i] * REL_STRIDE4], zeps, sf,
                        ov[3 * i], ov[3 * i + 1], ov[3 * i + 2]);
        }

        float4 *o4 = reinterpret_cast<float4 *>(out) + (size_t)q * 3;
        __stcs(o4 + 0, make_float4(ov[0], ov[1], ov[2],  ov[3]));
        __stcs(o4 + 1, make_float4(ov[4], ov[5], ov[6],  ov[7]));
        __stcs(o4 + 2, make_float4(ov[8], ov[9], ov[10], ov[11]));
    }

    // scalar tail (n % 4 rows) — empty for N = 8,000,000 but kept general
    int rem = n - nquads * 4;
    if (q < rem) {
        int i = nquads * 4 + q;
        float a0, a1, a2;
        row_compute(prnt[3 * i], prnt[3 * i + 1], prnt[3 * i + 2],
                    child[3 * i], child[3 * i + 1], child[3 * i + 2],
                    &sRel[rels[i] * REL_STRIDE4], zeps, sf, a0, a1, a2);
        out[3 * i] = a0; out[3 * i + 1] = a1; out[3 * i + 2] = a2;
    }
}

extern "C" void kernel_launch(void* const* d_in, const int* in_sizes, int n_in,
                              void* d_out, int out_size) {
    // metadata order: prnt_probs, child_probs, M, beta, z_epsilon, scale_factor, rels, var_sfx
    const float *prnt  = (const float *)d_in[0];
    const float *child = (const float *)d_in[1];
    const float *Mg    = (const float *)d_in[2];
    const float *betag = (const float *)d_in[3];
    const float *zeps  = (const float *)d_in[4];
    const float *sf    = (const float *)d_in[5];
    const int   *rels  = (const int *)d_in[6];
    float *out = (float *)d_out;

    int n = in_sizes[6];
    int nquads = n / 4;
    int work = nquads > 0 ? nquads : 1;
    int threads = 256;
    int blocks = (work + threads - 1) / threads;

    alpha_kernel<<<blocks, threads>>>(prnt, child, Mg, betag, zeps, sf, rels,
                                      out, n, nquads);
}

// round 5
// speedup vs baseline: 1.1318x; 1.0068x over previous
#include <cuda_runtime.h>
#include <cuda_bf16.h>

#define N_RELS 64
#define REL_STRIDE4 3   // 3 float4 per relation = 48B (M row + beta packed in .w)

// Sparsemax for d=3 via closed-form threshold:
//   tau = max_k (cs_k - 1)/k  == reference's (cs[ksup-1]-1)/ksup
// (support at k+1 <=> (cs_{k+1}-1)/(k+1) > (cs_k-1)/k, support prefix-closed).
static __device__ __forceinline__ void sparsemax3(float x0, float x1, float x2,
                                                  float &o0, float &o1, float &o2) {
    float mx  = fmaxf(fmaxf(x0, x1), x2);
    float mn  = fminf(fminf(x0, x1), x2);
    float sum = x0 + x1 + x2;
    float t1 = mx - 1.0f;
    float t2 = (sum - mn - 1.0f) * 0.5f;
    float t3 = (sum - 1.0f) * (1.0f / 3.0f);
    float tau = fmaxf(t1, fmaxf(t2, t3));
    o0 = fmaxf(x0 - tau, 0.0f);
    o1 = fmaxf(x1 - tau, 0.0f);
    o2 = fmaxf(x2 - tau, 0.0f);
}

static __device__ __forceinline__ void row_compute(
    float p0, float p1, float p2,
    float h0, float h1, float h2,
    const float4 *__restrict__ relp,
    float zeps, float sf,
    float &a0, float &a1, float &a2)
{
    float4 m0 = relp[0];   // {M00,M01,M02, beta0}
    float4 m1 = relp[1];   // {M10,M11,M12, beta1}
    float4 m2 = relp[2];   // {M20,M21,M22, beta2}

    // c = M[rel] @ child
    float c0 = m0.x * h0 + m0.y * h1 + m0.z * h2;
    float c1 = m1.x * h0 + m1.y * h1 + m1.z * h2;
    float c2 = m2.x * h0 + m2.y * h1 + m2.z * h2;
    sparsemax3(c0, c1, c2, c0, c1, c2);
    // (second sparsemax is an exact identity on a simplex point — dropped)
    sparsemax3(p0, p1, p2, p0, p1, p2);

    // alpha = (1-b)*p + b*c == p + b*(c-p)
    a0 = p0 + m0.w * (c0 - p0);
    a1 = p1 + m1.w * (c1 - p1);
    a2 = p2 + m2.w * (c2 - p2);

    // entropy of clamped normalized mixture (base-2; ln2 folded into divide)
    float w0 = fmaxf(p0 + c0, zeps);
    float w1 = fmaxf(p1 + c1, zeps);
    float w2 = fmaxf(p2 + c2, zeps);
    float inv = __fdividef(1.0f, w0 + w1 + w2);
    w0 *= inv; w1 *= inv; w2 *= inv;
    float t2 = w0 * __log2f(w0) + w1 * __log2f(w1) + w2 * __log2f(w2); // < 0

    // sparsemax outputs sum to 1 => max comp >= 1/3 => pp*cc >= 1/81:
    // reference's max(nrm,1e-10) guard is provably inactive.
    float dot = p0 * c0 + p1 * c1 + p2 * c2;
    float pp  = p0 * p0 + p1 * p1 + p2 * p2;
    float cc  = c0 * c0 + c1 * c1 + c2 * c2;
    float rq  = rsqrtf(pp * cc);
    float cosv = 0.1f + dot * rq;
    float scale = __fdividef(sf * cosv, -0.69314718056f * t2);

    a0 = fmaxf(a0 * scale, 0.001f);
    a1 = fmaxf(a1 * scale, 0.001f);
    a2 = fmaxf(a2 * scale, 0.001f);
}

// Compute one quad (4 rows) from preloaded registers.
static __device__ __forceinline__ void quad_compute(
    const float4 pA, const float4 pB, const float4 pC,
    const float4 cA, const float4 cB, const float4 cC,
    const int4 r4, const float4 *__restrict__ sRel,
    float zeps, float sf, float4 &oA, float4 &oB, float4 &oC)
{
    float pv[12] = {pA.x, pA.y, pA.z, pA.w, pB.x, pB.y, pB.z, pB.w,
                    pC.x, pC.y, pC.z, pC.w};
    float cv[12] = {cA.x, cA.y, cA.z, cA.w, cB.x, cB.y, cB.z, cB.w,
                    cC.x, cC.y, cC.z, cC.w};
    int rr[4] = {r4.x, r4.y, r4.z, r4.w};
    float ov[12];
#pragma unroll
    for (int i = 0; i < 4; i++) {
        row_compute(pv[3 * i], pv[3 * i + 1], pv[3 * i + 2],
                    cv[3 * i], cv[3 * i + 1], cv[3 * i + 2],
                    &sRel[rr[i] * REL_STRIDE4], zeps, sf,
                    ov[3 * i], ov[3 * i + 1], ov[3 * i + 2]);
    }
    oA = make_float4(ov[0], ov[1], ov[2],  ov[3]);
    oB = make_float4(ov[4], ov[5], ov[6],  ov[7]);
    oC = make_float4(ov[8], ov[9], ov[10], ov[11]);
}

__global__ void __launch_bounds__(256, 4)
alpha_kernel(const float *__restrict__ prnt,
             const float *__restrict__ child,
             const float *__restrict__ Mg,
             const float *__restrict__ betag,
             const float *__restrict__ zeps_p,
             const float *__restrict__ sf_p,
             const int *__restrict__ rels,
             float *__restrict__ out,
             int n, int nquads, int half)
{
    __shared__ float4 sRel[N_RELS * REL_STRIDE4];
    {
        float *sF = reinterpret_cast<float *>(sRel);
        for (int i = threadIdx.x; i < N_RELS * 12; i += blockDim.x) {
            int r = i / 12, j = i % 12;
            int row = j >> 2, c = j & 3;
            sF[r * 12 + j] = (c < 3) ? Mg[r * 9 + row * 3 + c]
                                     : betag[r * 3 + row];
        }
    }
    __syncthreads();

    const float zeps = __ldg(zeps_p);
    const float sf   = __ldg(sf_p);

    int idx = blockIdx.x * blockDim.x + threadIdx.x;
    const float4 *pr4 = reinterpret_cast<const float4 *>(prnt);
    const float4 *ch4 = reinterpret_cast<const float4 *>(child);
    const int4  *rl4  = reinterpret_cast<const int4 *>(rels);
    float4 *o4 = reinterpret_cast<float4 *>(out);

    int qa = idx;               // first quad
    int qb = half + idx;        // second quad (warp-coalesced group)
    bool da = qa < half;
    bool db = db = (qb < nquads);

    // ---- front-batch ALL global loads (max MLP) ----
    float4 paA, paB, paC, caA, caB, caC; int4 raQ;
    float4 pbA, pbB, pbC, cbA, cbB, cbC; int4 rbQ;
    if (da) {
        size_t o = (size_t)qa * 3;
        paA = __ldcs(pr4 + o);     paB = __ldcs(pr4 + o + 1); paC = __ldcs(pr4 + o + 2);
        caA = __ldcs(ch4 + o);     caB = __ldcs(ch4 + o + 1); caC = __ldcs(ch4 + o + 2);
        raQ = __ldcs(rl4 + qa);
    }
    if (db) {
        size_t o = (size_t)qb * 3;
        pbA = __ldcs(pr4 + o);     pbB = __ldcs(pr4 + o + 1); pbC = __ldcs(pr4 + o + 2);
        cbA = __ldcs(ch4 + o);     cbB = __ldcs(ch4 + o + 1); cbC = __ldcs(ch4 + o + 2);
        rbQ = __ldcs(rl4 + qb);
    }

    if (da) {
        float4 oA, oB, oC;
        quad_compute(paA, paB, paC, caA, caB, caC, raQ, sRel, zeps, sf, oA, oB, oC);
        size_t o = (size_t)qa * 3;
        __stcs(o4 + o, oA); __stcs(o4 + o + 1, oB); __stcs(o4 + o + 2, oC);
    }
    if (db) {
        float4 oA, oB, oC;
        quad_compute(pbA, pbB, pbC, cbA, cbB, cbC, rbQ, sRel, zeps, sf, oA, oB, oC);
        size_t o = (size_t)qb * 3;
        __stcs(o4 + o, oA); __stcs(o4 + o + 1, oB); __stcs(o4 + o + 2, oC);
    }

    // scalar tail (n % 4 rows) — empty for N = 8,000,000 but kept general
    int rem = n - nquads * 4;
    if (idx < rem) {
        int i = nquads * 4 + idx;
        float a0, a1, a2;
        row_compute(prnt[3 * i], prnt[3 * i + 1], prnt[3 * i + 2],
                    child[3 * i], child[3 * i + 1], child[3 * i + 2],
                    &sRel[rels[i] * REL_STRIDE4], zeps, sf, a0, a1, a2);
        out[3 * i] = a0; out[3 * i + 1] = a1; out[3 * i + 2] = a2;
    }
}

extern "C" void kernel_launch(void* const* d_in, const int* in_sizes, int n_in,
                              void* d_out, int out_size) {
    // metadata order: prnt_probs, child_probs, M, beta, z_epsilon, scale_factor, rels, var_sfx
    const float *prnt  = (const float *)d_in[0];
    const float *child = (const float *)d_in[1];
    const float *Mg    = (const float *)d_in[2];
    const float *betag = (const float *)d_in[3];
    const float *zeps  = (const float *)d_in[4];
    const float *sf    = (const float *)d_in[5];
    const int   *rels  = (const int *)d_in[6];
    float *out = (float *)d_out;

    int n = in_sizes[6];
    int nquads = n / 4;
    int half = (nquads + 1) / 2;
    int work = half > 0 ? half : 1;
    int threads = 256;
    int blocks = (work + threads - 1) / threads;

    alpha_kernel<<<blocks, threads>>>(prnt, child, Mg, betag, zeps, sf, rels,
                                      out, n, nquads, half);
}